// round 2
// baseline (speedup 1.0000x reference)
#include <cuda_runtime.h>
#include <math.h>

// Problem constants
#define Bb   2
#define Ls   4096
#define Dd   1024
#define ORD  2
#define EMBn 3
#define FOn  64
#define PROJ_N (3*Dd)
// Filter truncation: window = exp(-0.5 * n * 4096/4095) -> tap64/tap0 ~ e^-32 ~ 1e-14
#define TAPS 64

// ---------------- scratch (device globals; no allocations allowed) -------------
__device__ float g_proj[(size_t)Bb*Ls*3*Dd]; // 96 MB
__device__ float g_h[(size_t)TAPS*Dd];       // truncated filter
__device__ float g_v[(size_t)Bb*Ls*Dd];      // current v
__device__ float g_u[(size_t)Bb*Ls*Dd];      // long-conv output
__device__ float g_xc[(size_t)Bb*Ls*Dd];     // depthwise-3 conv output

__device__ __forceinline__ float gelu_exact(float x) {
    return 0.5f * x * (1.0f + erff(x * 0.70710678118654752f));
}

// ---------------- generic fp32 SGEMM: C = A(MxK) @ B(KxN) + bias ---------------
// epi==1: C = u .* xcm .* sigmoid(A@B + bias)   (N must equal Dd row stride of u/xcm)
__global__ void __launch_bounds__(256) sgemm_k(
    const float* __restrict__ A, const float* __restrict__ B,
    const float* __restrict__ bias, float* __restrict__ C,
    int M, int N, int K, int epi,
    const float* __restrict__ u, const float* __restrict__ xcm)
{
    constexpr int BM = 128, BN = 128, BK = 16;
    __shared__ float As[BK][BM + 4];
    __shared__ float Bs[BK][BN + 4];

    const int tid  = threadIdx.x;
    const int bm   = blockIdx.y * BM;
    const int bn   = blockIdx.x * BN;
    const int ar   = tid >> 2;          // 0..63
    const int ac   = (tid & 3) << 2;    // 0,4,8,12
    const int br   = tid >> 5;          // 0..7
    const int bc   = (tid & 31) << 2;   // 0..124
    const int trow = (tid >> 4) << 3;   // 0..120
    const int tcol = (tid & 15) << 3;   // 0..120

    float acc[8][8];
    #pragma unroll
    for (int i = 0; i < 8; i++)
        #pragma unroll
        for (int j = 0; j < 8; j++) acc[i][j] = 0.f;

    for (int k0 = 0; k0 < K; k0 += BK) {
        #pragma unroll
        for (int i = 0; i < 2; i++) {
            float4 a = *(const float4*)(A + (size_t)(bm + ar + 64*i) * K + k0 + ac);
            As[ac+0][ar + 64*i] = a.x;
            As[ac+1][ar + 64*i] = a.y;
            As[ac+2][ar + 64*i] = a.z;
            As[ac+3][ar + 64*i] = a.w;
        }
        #pragma unroll
        for (int i = 0; i < 2; i++) {
            *(float4*)&Bs[br + 8*i][bc] =
                *(const float4*)(B + (size_t)(k0 + br + 8*i) * N + bn + bc);
        }
        __syncthreads();

        #pragma unroll
        for (int kk = 0; kk < BK; kk++) {
            float a0[8], b0[8];
            *(float4*)&a0[0] = *(const float4*)&As[kk][trow];
            *(float4*)&a0[4] = *(const float4*)&As[kk][trow + 4];
            *(float4*)&b0[0] = *(const float4*)&Bs[kk][tcol];
            *(float4*)&b0[4] = *(const float4*)&Bs[kk][tcol + 4];
            #pragma unroll
            for (int i = 0; i < 8; i++)
                #pragma unroll
                for (int j = 0; j < 8; j++)
                    acc[i][j] = fmaf(a0[i], b0[j], acc[i][j]);
        }
        __syncthreads();
    }

    #pragma unroll
    for (int i = 0; i < 8; i++) {
        int m = bm + trow + i;
        size_t rowo = (size_t)m * N + bn + tcol;
        #pragma unroll
        for (int jj = 0; jj < 8; jj += 4) {
            float4 o;
            #pragma unroll
            for (int q = 0; q < 4; q++) {
                int n = bn + tcol + jj + q;
                float val = acc[i][jj + q] + bias[n];
                if (epi == 1) {
                    size_t idx = (size_t)m * N + n;
                    float gte = 1.0f / (1.0f + expf(-val));
                    val = u[idx] * xcm[idx] * gte;
                }
                ((float*)&o)[q] = val;
            }
            *(float4*)(C + rowo + jj) = o;
        }
    }
}

// ---------------- implicit filter: h[n,d] for n < TAPS -------------------------
__global__ void filter_k(const float* __restrict__ freqs,
                         const float* __restrict__ w1, const float* __restrict__ b1,
                         const float* __restrict__ w2, const float* __restrict__ b2,
                         const float* __restrict__ w3, const float* __restrict__ b3,
                         const float* __restrict__ decay, int ord,
                         float* __restrict__ h)
{
    const int n   = blockIdx.x;     // 0..TAPS-1
    const int tid = threadIdx.x;    // 256 threads
    const float t = (float)n / (float)(Ls - 1);

    __shared__ float h1s[FOn];
    __shared__ float h2s[FOn];

    float enc[7];
    const float* f = freqs + ord * EMBn;
    #pragma unroll
    for (int j = 0; j < 3; j++) {
        float ang = 6.283185307179586f * f[j] * t;
        enc[j]     = sinf(ang);
        enc[3 + j] = cosf(ang);
    }
    enc[6] = t;

    if (tid < FOn) {
        float s = b1[ord * FOn + tid];
        #pragma unroll
        for (int k = 0; k < 7; k++)
            s += enc[k] * w1[(ord * 7 + k) * FOn + tid];
        h1s[tid] = gelu_exact(s);
    }
    __syncthreads();
    if (tid < FOn) {
        float s = b2[ord * FOn + tid];
        for (int k = 0; k < FOn; k++)
            s += h1s[k] * w2[(ord * FOn + k) * FOn + tid];
        h2s[tid] = gelu_exact(s);
    }
    __syncthreads();

    for (int d = tid; d < Dd; d += blockDim.x) {
        float s = b3[(size_t)ord * Dd + d];
        for (int k = 0; k < FOn; k++)
            s += h2s[k] * w3[((size_t)ord * FOn + k) * Dd + d];
        float wind = expf(-fabsf(decay[(size_t)ord * Dd + d]) * t * (float)Ls);
        h[(size_t)n * Dd + d] = s * wind;
    }
}

// ---------------- truncated causal depthwise long conv -------------------------
// y[b,t,d] = sum_{l=0}^{TAPS-1} h[l,d] * v[b,t-l,d]
#define CT 32
__global__ void __launch_bounds__(128) convlong_k(
    const float* __restrict__ vin, int vstride,
    const float* __restrict__ h, float* __restrict__ y)
{
    __shared__ float vs[CT + TAPS - 1][128];   // 95 x 128 floats = 47.5 KB

    const int tx = threadIdx.x;
    const int d  = blockIdx.x * 128 + tx;
    const int t0 = blockIdx.y * CT;
    const int b  = blockIdx.z;

    #pragma unroll 5
    for (int r = 0; r < CT + TAPS - 1; r++) {
        int t = t0 - (TAPS - 1) + r;
        vs[r][tx] = (t >= 0) ? vin[((size_t)b * Ls + t) * vstride + d] : 0.f;
    }
    __syncthreads();

    float acc[CT];
    #pragma unroll
    for (int j = 0; j < CT; j++) acc[j] = 0.f;

    #pragma unroll
    for (int l0 = 0; l0 < TAPS; l0 += 16) {
        float hr[16];
        #pragma unroll
        for (int l = 0; l < 16; l++)
            hr[l] = h[(size_t)(l0 + l) * Dd + d];
        float vv[CT + 15];
        #pragma unroll
        for (int q = 0; q < CT + 15; q++)
            vv[q] = vs[(TAPS - 1 - 15) - l0 + q][tx];
        #pragma unroll
        for (int l = 0; l < 16; l++)
            #pragma unroll
            for (int j = 0; j < CT; j++)
                acc[j] = fmaf(vv[15 + j - l], hr[l], acc[j]);
    }

    #pragma unroll
    for (int j = 0; j < CT; j++)
        y[((size_t)b * Ls + t0 + j) * Dd + d] = acc[j];
}

// ---------------- depthwise K=3 conv + bias ------------------------------------
__global__ void conv3_k(const float* __restrict__ proj, int stride, int off,
                        const float* __restrict__ w, const float* __restrict__ cb,
                        float* __restrict__ xc)
{
    size_t idx = (size_t)blockIdx.x * blockDim.x + threadIdx.x;
    if (idx >= (size_t)Bb * Ls * Dd) return;
    int d = (int)(idx & (Dd - 1));
    size_t bt = idx >> 10;           // Dd = 1024
    int t = (int)(bt & (Ls - 1));
    const float* base = proj + bt * (size_t)stride + off + d;
    float s = cb[d] + base[0] * w[Dd + d];
    if (t > 0)      s += base[-(ptrdiff_t)stride] * w[d];
    if (t < Ls - 1) s += base[stride] * w[2 * Dd + d];
    xc[idx] = s;
}

// -------------------------------------------------------------------------------
extern "C" void kernel_launch(void* const* d_in, const int* in_sizes, int n_in,
                              void* d_out, int out_size)
{
    const float* x    = (const float*)d_in[0];
    const float* ipw  = (const float*)d_in[1];
    const float* ipb  = (const float*)d_in[2];
    const float* opw  = (const float*)d_in[3];
    const float* opb  = (const float*)d_in[4];
    const float* fre  = (const float*)d_in[5];
    const float* w1   = (const float*)d_in[6];
    const float* b1   = (const float*)d_in[7];
    const float* w2   = (const float*)d_in[8];
    const float* b2   = (const float*)d_in[9];
    const float* w3   = (const float*)d_in[10];
    const float* b3   = (const float*)d_in[11];
    const float* dec  = (const float*)d_in[12];
    const float* cw   = (const float*)d_in[13];
    const float* cb   = (const float*)d_in[14];
    const float* gw   = (const float*)d_in[15];
    const float* gb   = (const float*)d_in[16];
    float* out = (float*)d_out;

    float *p_proj, *p_h, *p_v, *p_u, *p_xc;
    cudaGetSymbolAddress((void**)&p_proj, g_proj);
    cudaGetSymbolAddress((void**)&p_h,    g_h);
    cudaGetSymbolAddress((void**)&p_v,    g_v);
    cudaGetSymbolAddress((void**)&p_u,    g_u);
    cudaGetSymbolAddress((void**)&p_xc,   g_xc);

    const int M = Bb * Ls;   // 8192

    // 1) proj = x @ in_proj_w + in_proj_b   (M x 3072)
    {
        dim3 g(PROJ_N / 128, M / 128);
        sgemm_k<<<g, 256>>>(x, ipw, ipb, p_proj, M, PROJ_N, Dd, 0, nullptr, nullptr);
    }

    for (int i = 0; i < ORD; i++) {
        // 2a) truncated implicit filter
        filter_k<<<TAPS, 256>>>(fre, w1, b1, w2, b2, w3, b3, dec, i, p_h);

        // 2b) long causal depthwise conv (v0 lives inside proj at offset 0, stride 3D)
        const float* vin = (i == 0) ? p_proj : p_v;
        int vstride      = (i == 0) ? PROJ_N : Dd;
        dim3 gc(Dd / 128, Ls / CT, Bb);
        convlong_k<<<gc, 128>>>(vin, vstride, p_h, p_u);

        // 2c) depthwise-3 conv on ctrl slice
        conv3_k<<<(Bb * Ls * Dd) / 256, 256>>>(p_proj, PROJ_N, (i + 1) * Dd,
                                               cw + (size_t)i * 3 * Dd,
                                               cb + (size_t)i * Dd, p_xc);

        // 2d) gate GEMM fused with  v = u .* xc .* sigmoid(xc@gw + gb)
        dim3 gg(Dd / 128, M / 128);
        sgemm_k<<<gg, 256>>>(p_xc, gw + (size_t)i * Dd * Dd, gb + (size_t)i * Dd,
                             p_v, M, Dd, Dd, 1, p_u, p_xc);
    }

    // 3) out = v @ out_proj_w + out_proj_b
    {
        dim3 g(Dd / 128, M / 128);
        sgemm_k<<<g, 256>>>(p_v, opw, opb, out, M, Dd, Dd, 0, nullptr, nullptr);
    }
}

// round 4
// speedup vs baseline: 2.2028x; 2.2028x over previous
#include <cuda_runtime.h>
#include <cuda_bf16.h>
#include <math.h>
#include <stdint.h>

// Problem constants
#define Bb     2
#define Ls     4096
#define Dd     1024
#define ORD    2
#define PROJ_N (3*Dd)
#define TAPS   64
#define Mrows  (Bb*Ls)        // 8192
#define KDIM   1024
#define WROWS  (PROJ_N + 3*Dd)   // 6144 transposed weight rows

// ---------------- scratch (device globals) -------------------------------------
__device__ float g_proj[(size_t)Mrows*PROJ_N]; // 96 MB
__device__ float g_h[(size_t)TAPS*Dd];
__device__ float g_v[(size_t)Mrows*Dd];
__device__ float g_u[(size_t)Mrows*Dd];
__device__ float g_xc[(size_t)Mrows*Dd];
__device__ __nv_bfloat16 g_w0[(size_t)WROWS*KDIM];
__device__ __nv_bfloat16 g_w1[(size_t)WROWS*KDIM];
__device__ __nv_bfloat16 g_a0[(size_t)Mrows*KDIM];
__device__ __nv_bfloat16 g_a1[(size_t)Mrows*KDIM];
__device__ __nv_bfloat16 g_c0[(size_t)Mrows*KDIM];
__device__ __nv_bfloat16 g_c1[(size_t)Mrows*KDIM];
__device__ __nv_bfloat16 g_v0[(size_t)Mrows*KDIM];
__device__ __nv_bfloat16 g_v1[(size_t)Mrows*KDIM];

// ---------------- helpers -------------------------------------------------------
__device__ __forceinline__ uint32_t smem_u32(const void* p) {
    uint32_t a;
    asm("{ .reg .u64 t; cvta.to.shared.u64 t, %1; cvt.u32.u64 %0, t; }" : "=r"(a) : "l"(p));
    return a;
}
__device__ __forceinline__ void ldsm4(uint32_t* r, uint32_t addr) {
    asm volatile("ldmatrix.sync.aligned.m8n8.x4.shared.b16 {%0,%1,%2,%3}, [%4];"
                 : "=r"(r[0]), "=r"(r[1]), "=r"(r[2]), "=r"(r[3]) : "r"(addr));
}
__device__ __forceinline__ void mma16816(float* c, const uint32_t* a, const uint32_t* b) {
    asm volatile(
        "mma.sync.aligned.m16n8k16.row.col.f32.bf16.bf16.f32 "
        "{%0,%1,%2,%3}, {%4,%5,%6,%7}, {%8,%9}, {%0,%1,%2,%3};"
        : "+f"(c[0]), "+f"(c[1]), "+f"(c[2]), "+f"(c[3])
        : "r"(a[0]), "r"(a[1]), "r"(a[2]), "r"(a[3]), "r"(b[0]), "r"(b[1]));
}

// ================== bf16x3 HMMA GEMM =============================================
// C[M,N] = A[M,K] @ Bt[N,K]^T (+bias).  A,B as 2 bf16 components each.
// CTA tile 128x128, K chunk 64, 3-stage cp.async pipeline, SW128 swizzle.
#define STAGES      3
#define CHUNK_K     64
#define STAGE_BYTES 65536      // A0,A1,B0,B1 x 16KB
#define GEMM_SMEM   (STAGES*STAGE_BYTES)

__global__ void __launch_bounds__(256, 1) gemm_bf16x3_k(
    const __nv_bfloat16* __restrict__ A0, const __nv_bfloat16* __restrict__ A1,
    const __nv_bfloat16* __restrict__ B0, const __nv_bfloat16* __restrict__ B1,
    const float* __restrict__ bias, float* __restrict__ C, int ldc, int Kdim, int epi,
    const float* __restrict__ u, const float* __restrict__ xcm,
    __nv_bfloat16* __restrict__ v0, __nv_bfloat16* __restrict__ v1)
{
    extern __shared__ char smem[];
    const uint32_t stg = smem_u32(smem);
    const int tid = threadIdx.x, wid = tid >> 5, lane = tid & 31;
    const int bm = blockIdx.y * 128, bn = blockIdx.x * 128;
    const int wm = (wid & 3) * 32, wn = (wid >> 2) * 64;
    const int nchunk = Kdim / CHUNK_K;

    const __nv_bfloat16* sA0 = A0 + (size_t)bm * Kdim;
    const __nv_bfloat16* sA1 = A1 + (size_t)bm * Kdim;
    const __nv_bfloat16* sB0 = B0 + (size_t)bn * Kdim;
    const __nv_bfloat16* sB1 = B1 + (size_t)bn * Kdim;

    auto fill = [&](int chunk, int stage) {
        const uint32_t st = stg + stage * STAGE_BYTES;
        const int k0 = chunk * CHUNK_K;
        const __nv_bfloat16* gs[4] = { sA0, sA1, sB0, sB1 };
        #pragma unroll
        for (int sub = 0; sub < 4; sub++) {
            const __nv_bfloat16* g = gs[sub] + k0;
            const uint32_t db = st + sub * 16384;
            #pragma unroll
            for (int i = 0; i < 4; i++) {
                int idx = tid + i * 256;            // 0..1023
                int row = idx >> 3, cs = idx & 7;   // 128 rows x 8 chunks of 16B
                const void* gp = g + (size_t)row * Kdim + cs * 8;
                uint32_t dp = db + row * 128 + ((cs ^ (row & 7)) << 4);
                asm volatile("cp.async.cg.shared.global [%0], [%1], 16;"
                             :: "r"(dp), "l"(gp) : "memory");
            }
        }
        asm volatile("cp.async.commit_group;" ::: "memory");
    };

    fill(0, 0);
    fill(1, 1);

    float acc[2][8][4];
    #pragma unroll
    for (int i = 0; i < 2; i++)
        #pragma unroll
        for (int j = 0; j < 8; j++)
            #pragma unroll
            for (int q = 0; q < 4; q++) acc[i][j][q] = 0.f;

    // per-lane swizzled ldmatrix offsets (stage-invariant)
    uint32_t offA[2][4], offB[4][4];
    #pragma unroll
    for (int mt = 0; mt < 2; mt++) {
        int row = wm + mt * 16 + (lane & 15);
        #pragma unroll
        for (int kk = 0; kk < 4; kk++) {
            int cs = kk * 2 + (lane >> 4);
            offA[mt][kk] = row * 128 + ((cs ^ (row & 7)) << 4);
        }
    }
    #pragma unroll
    for (int j = 0; j < 4; j++) {
        int n = wn + j * 16 + ((lane >> 4) << 3) + (lane & 7);
        #pragma unroll
        for (int kk = 0; kk < 4; kk++) {
            int cs = kk * 2 + ((lane >> 3) & 1);
            offB[j][kk] = n * 128 + ((cs ^ (n & 7)) << 4);
        }
    }

    for (int c = 0; c < nchunk; c++) {
        const int s = c % STAGES;
        asm volatile("cp.async.wait_group 1;" ::: "memory");
        __syncthreads();

        const int nc = c + STAGES - 1;
        if (nc < nchunk) fill(nc, nc % STAGES);

        const uint32_t st = stg + s * STAGE_BYTES;
        #pragma unroll
        for (int kk = 0; kk < 4; kk++) {
            uint32_t a[2][2][4];                   // [comp][mt][4]
            #pragma unroll
            for (int mt = 0; mt < 2; mt++) {
                ldsm4(a[0][mt], st + offA[mt][kk]);
                ldsm4(a[1][mt], st + 16384 + offA[mt][kk]);
            }
            uint32_t b[2][8][2];                   // [comp][ntile][2]
            #pragma unroll
            for (int j = 0; j < 4; j++) {
                uint32_t r[4];
                ldsm4(r, st + 32768 + offB[j][kk]);
                b[0][2*j][0] = r[0]; b[0][2*j][1] = r[1];
                b[0][2*j+1][0] = r[2]; b[0][2*j+1][1] = r[3];
                ldsm4(r, st + 49152 + offB[j][kk]);
                b[1][2*j][0] = r[0]; b[1][2*j][1] = r[1];
                b[1][2*j+1][0] = r[2]; b[1][2*j+1][1] = r[3];
            }
            #pragma unroll
            for (int mt = 0; mt < 2; mt++)
                #pragma unroll
                for (int nt = 0; nt < 8; nt++) {
                    mma16816(acc[mt][nt], a[0][mt], b[0][nt]);   // h*h
                    mma16816(acc[mt][nt], a[0][mt], b[1][nt]);   // h*l
                    mma16816(acc[mt][nt], a[1][mt], b[0][nt]);   // l*h
                }
        }
    }

    // ---------------- epilogue --------------------------------------------------
    const int r0 = bm + wm + (lane >> 2);
    const int cb0 = bn + wn + (lane & 3) * 2;
    #pragma unroll
    for (int mt = 0; mt < 2; mt++) {
        #pragma unroll
        for (int nt = 0; nt < 8; nt++) {
            const int col = cb0 + nt * 8;
            const float bx = bias[col], by = bias[col + 1];
            #pragma unroll
            for (int half = 0; half < 2; half++) {
                const int row = r0 + mt * 16 + half * 8;
                float vx = acc[mt][nt][half * 2 + 0] + bx;
                float vy = acc[mt][nt][half * 2 + 1] + by;
                if (epi == 1) {
                    const size_t idx = (size_t)row * Dd + col;
                    float2 uu = *(const float2*)(u + idx);
                    float2 xx = *(const float2*)(xcm + idx);
                    vx = uu.x * xx.x * (1.0f / (1.0f + expf(-vx)));
                    vy = uu.y * xx.y * (1.0f / (1.0f + expf(-vy)));
                    __nv_bfloat16 h0 = __float2bfloat16_rn(vx);
                    __nv_bfloat16 h1 = __float2bfloat16_rn(vy);
                    __nv_bfloat162 hh; hh.x = h0; hh.y = h1;
                    *(__nv_bfloat162*)(v0 + idx) = hh;
                    __nv_bfloat162 ll;
                    ll.x = __float2bfloat16_rn(vx - __bfloat162float(h0));
                    ll.y = __float2bfloat16_rn(vy - __bfloat162float(h1));
                    *(__nv_bfloat162*)(v1 + idx) = ll;
                }
                float2 o; o.x = vx; o.y = vy;
                *(float2*)(C + (size_t)row * ldc + col) = o;
            }
        }
    }
}

// ================== split / transpose-split ======================================
__global__ void split4_k(const float* __restrict__ s,
                         __nv_bfloat16* __restrict__ b0, __nv_bfloat16* __restrict__ b1, int n4)
{
    int i = blockIdx.x * blockDim.x + threadIdx.x;
    if (i >= n4) return;
    float4 v = ((const float4*)s)[i];
    const float* vv = (const float*)&v;
    #pragma unroll
    for (int q = 0; q < 4; q += 2) {
        __nv_bfloat16 h0 = __float2bfloat16_rn(vv[q]);
        __nv_bfloat16 h1 = __float2bfloat16_rn(vv[q + 1]);
        __nv_bfloat162 hh; hh.x = h0; hh.y = h1;
        *(__nv_bfloat162*)(b0 + (size_t)i * 4 + q) = hh;
        __nv_bfloat162 ll;
        ll.x = __float2bfloat16_rn(vv[q]     - __bfloat162float(h0));
        ll.y = __float2bfloat16_rn(vv[q + 1] - __bfloat162float(h1));
        *(__nv_bfloat162*)(b1 + (size_t)i * 4 + q) = ll;
    }
}

__global__ void tsplit_k(const float* __restrict__ W, int N, int rowoff,
                         __nv_bfloat16* __restrict__ T0, __nv_bfloat16* __restrict__ T1)
{
    __shared__ float tile[32][33];
    int n0 = blockIdx.x * 32, k0 = blockIdx.y * 32;
    int tx = threadIdx.x, ty = threadIdx.y;   // 32 x 8
    #pragma unroll
    for (int j = 0; j < 32; j += 8)
        tile[ty + j][tx] = W[(size_t)(k0 + ty + j) * N + n0 + tx];
    __syncthreads();
    #pragma unroll
    for (int j = 0; j < 32; j += 8) {
        int n = n0 + ty + j, k = k0 + tx;
        float v = tile[tx][ty + j];
        __nv_bfloat16 h = __float2bfloat16_rn(v);
        size_t o = (size_t)(rowoff + n) * KDIM + k;
        T0[o] = h;
        T1[o] = __float2bfloat16_rn(v - __bfloat162float(h));
    }
}

// ================== filter / convs ===============================================
__device__ __forceinline__ float gelu_exact(float x) {
    return 0.5f * x * (1.0f + erff(x * 0.70710678118654752f));
}

__global__ void filter_k(const float* __restrict__ freqs,
                         const float* __restrict__ w1, const float* __restrict__ b1,
                         const float* __restrict__ w2, const float* __restrict__ b2,
                         const float* __restrict__ w3, const float* __restrict__ b3,
                         const float* __restrict__ decay, int ord,
                         float* __restrict__ h)
{
    const int n   = blockIdx.x;
    const int tid = threadIdx.x;
    const float t = (float)n / (float)(Ls - 1);
    __shared__ float h1s[64];
    __shared__ float h2s[64];
    float enc[7];
    const float* f = freqs + ord * 3;
    #pragma unroll
    for (int j = 0; j < 3; j++) {
        float ang = 6.283185307179586f * f[j] * t;
        enc[j] = sinf(ang); enc[3 + j] = cosf(ang);
    }
    enc[6] = t;
    if (tid < 64) {
        float s = b1[ord * 64 + tid];
        #pragma unroll
        for (int k = 0; k < 7; k++) s += enc[k] * w1[(ord * 7 + k) * 64 + tid];
        h1s[tid] = gelu_exact(s);
    }
    __syncthreads();
    if (tid < 64) {
        float s = b2[ord * 64 + tid];
        for (int k = 0; k < 64; k++) s += h1s[k] * w2[(ord * 64 + k) * 64 + tid];
        h2s[tid] = gelu_exact(s);
    }
    __syncthreads();
    for (int d = tid; d < Dd; d += blockDim.x) {
        float s = b3[(size_t)ord * Dd + d];
        for (int k = 0; k < 64; k++) s += h2s[k] * w3[((size_t)ord * 64 + k) * Dd + d];
        float wind = expf(-fabsf(decay[(size_t)ord * Dd + d]) * t * (float)Ls);
        h[(size_t)n * Dd + d] = s * wind;
    }
}

#define CT 32
__global__ void __launch_bounds__(128) convlong_k(
    const float* __restrict__ vin, int vstride,
    const float* __restrict__ h, float* __restrict__ y)
{
    __shared__ float vs[CT + TAPS - 1][128];
    const int tx = threadIdx.x;
    const int d  = blockIdx.x * 128 + tx;
    const int t0 = blockIdx.y * CT;
    const int b  = blockIdx.z;
    #pragma unroll 5
    for (int r = 0; r < CT + TAPS - 1; r++) {
        int t = t0 - (TAPS - 1) + r;
        vs[r][tx] = (t >= 0) ? vin[((size_t)b * Ls + t) * vstride + d] : 0.f;
    }
    __syncthreads();
    float acc[CT];
    #pragma unroll
    for (int j = 0; j < CT; j++) acc[j] = 0.f;
    #pragma unroll
    for (int l0 = 0; l0 < TAPS; l0 += 16) {
        float hr[16];
        #pragma unroll
        for (int l = 0; l < 16; l++) hr[l] = h[(size_t)(l0 + l) * Dd + d];
        float vv[CT + 15];
        #pragma unroll
        for (int q = 0; q < CT + 15; q++) vv[q] = vs[(TAPS - 1 - 15) - l0 + q][tx];
        #pragma unroll
        for (int l = 0; l < 16; l++)
            #pragma unroll
            for (int j = 0; j < CT; j++)
                acc[j] = fmaf(vv[15 + j - l], hr[l], acc[j]);
    }
    #pragma unroll
    for (int j = 0; j < CT; j++)
        y[((size_t)b * Ls + t0 + j) * Dd + d] = acc[j];
}

// depthwise K=3 conv + bias, emits fp32 and bf16-split results
__global__ void conv3_k(const float* __restrict__ proj, int stride, int off,
                        const float* __restrict__ w, const float* __restrict__ cb,
                        float* __restrict__ xc,
                        __nv_bfloat16* __restrict__ o0, __nv_bfloat16* __restrict__ o1)
{
    size_t idx = (size_t)blockIdx.x * blockDim.x + threadIdx.x;
    if (idx >= (size_t)Mrows * Dd) return;
    int d = (int)(idx & (Dd - 1));
    size_t bt = idx >> 10;
    int t = (int)(bt & (Ls - 1));
    const float* base = proj + bt * (size_t)stride + off + d;
    float s = cb[d] + base[0] * w[Dd + d];
    if (t > 0)      s += base[-(ptrdiff_t)stride] * w[d];
    if (t < Ls - 1) s += base[stride] * w[2 * Dd + d];
    xc[idx] = s;
    __nv_bfloat16 h = __float2bfloat16_rn(s);
    o0[idx] = h;
    o1[idx] = __float2bfloat16_rn(s - __bfloat162float(h));
}

// =================================================================================
extern "C" void kernel_launch(void* const* d_in, const int* in_sizes, int n_in,
                              void* d_out, int out_size)
{
    const float* x    = (const float*)d_in[0];
    const float* ipw  = (const float*)d_in[1];
    const float* ipb  = (const float*)d_in[2];
    const float* opw  = (const float*)d_in[3];
    const float* opb  = (const float*)d_in[4];
    const float* fre  = (const float*)d_in[5];
    const float* w1   = (const float*)d_in[6];
    const float* b1   = (const float*)d_in[7];
    const float* w2   = (const float*)d_in[8];
    const float* b2   = (const float*)d_in[9];
    const float* w3   = (const float*)d_in[10];
    const float* b3   = (const float*)d_in[11];
    const float* dec  = (const float*)d_in[12];
    const float* cw   = (const float*)d_in[13];
    const float* cb   = (const float*)d_in[14];
    const float* gw   = (const float*)d_in[15];
    const float* gb   = (const float*)d_in[16];
    float* out = (float*)d_out;

    float *p_proj, *p_h, *p_v, *p_u, *p_xc;
    __nv_bfloat16 *p_w0, *p_w1, *p_a0, *p_a1, *p_c0, *p_c1, *p_v0, *p_v1;
    cudaGetSymbolAddress((void**)&p_proj, g_proj);
    cudaGetSymbolAddress((void**)&p_h,    g_h);
    cudaGetSymbolAddress((void**)&p_v,    g_v);
    cudaGetSymbolAddress((void**)&p_u,    g_u);
    cudaGetSymbolAddress((void**)&p_xc,   g_xc);
    cudaGetSymbolAddress((void**)&p_w0,   g_w0);
    cudaGetSymbolAddress((void**)&p_w1,   g_w1);
    cudaGetSymbolAddress((void**)&p_a0,   g_a0);
    cudaGetSymbolAddress((void**)&p_a1,   g_a1);
    cudaGetSymbolAddress((void**)&p_c0,   g_c0);
    cudaGetSymbolAddress((void**)&p_c1,   g_c1);
    cudaGetSymbolAddress((void**)&p_v0,   g_v0);
    cudaGetSymbolAddress((void**)&p_v1,   g_v1);

    cudaFuncSetAttribute(gemm_bf16x3_k, cudaFuncAttributeMaxDynamicSharedMemorySize, GEMM_SMEM);

    // split x into bf16 comps
    {
        int n4 = Mrows * KDIM / 4;
        split4_k<<<(n4 + 255) / 256, 256>>>(x, p_a0, p_a1, n4);
    }
    // transpose-split weights
    {
        dim3 b(32, 8);
        tsplit_k<<<dim3(PROJ_N / 32, KDIM / 32), b>>>(ipw, PROJ_N, 0,        p_w0, p_w1);
        tsplit_k<<<dim3(Dd / 32,     KDIM / 32), b>>>(gw,  Dd, PROJ_N,       p_w0, p_w1);
        tsplit_k<<<dim3(Dd / 32,     KDIM / 32), b>>>(gw + (size_t)Dd * Dd, Dd, PROJ_N + Dd, p_w0, p_w1);
        tsplit_k<<<dim3(Dd / 32,     KDIM / 32), b>>>(opw, Dd, PROJ_N + 2 * Dd, p_w0, p_w1);
    }

    // 1) proj = x @ in_proj_w + b
    gemm_bf16x3_k<<<dim3(PROJ_N / 128, Mrows / 128), 256, GEMM_SMEM>>>(
        p_a0, p_a1, p_w0, p_w1, ipb, p_proj, PROJ_N, KDIM, 0,
        nullptr, nullptr, nullptr, nullptr);

    for (int i = 0; i < ORD; i++) {
        filter_k<<<TAPS, 256>>>(fre, w1, b1, w2, b2, w3, b3, dec, i, p_h);

        const float* vin = (i == 0) ? p_proj : p_v;
        int vstride      = (i == 0) ? PROJ_N : Dd;
        dim3 gc(Dd / 128, Ls / CT, Bb);
        convlong_k<<<gc, 128>>>(vin, vstride, p_h, p_u);

        conv3_k<<<(Mrows * Dd) / 256, 256>>>(p_proj, PROJ_N, (i + 1) * Dd,
                                             cw + (size_t)i * 3 * Dd,
                                             cb + (size_t)i * Dd, p_xc, p_c0, p_c1);

        // gate GEMM fused: v = u .* xc .* sigmoid(xc@gw + gb), emits v bf16 comps
        gemm_bf16x3_k<<<dim3(Dd / 128, Mrows / 128), 256, GEMM_SMEM>>>(
            p_c0, p_c1,
            p_w0 + (size_t)(PROJ_N + i * Dd) * KDIM,
            p_w1 + (size_t)(PROJ_N + i * Dd) * KDIM,
            gb + (size_t)i * Dd, p_v, Dd, KDIM, 1,
            p_u, p_xc, p_v0, p_v1);
    }

    // 3) out = v @ out_proj_w + b
    gemm_bf16x3_k<<<dim3(Dd / 128, Mrows / 128), 256, GEMM_SMEM>>>(
        p_v0, p_v1,
        p_w0 + (size_t)(PROJ_N + 2 * Dd) * KDIM,
        p_w1 + (size_t)(PROJ_N + 2 * Dd) * KDIM,
        opb, out, Dd, KDIM, 0,
        nullptr, nullptr, nullptr, nullptr);
}

// round 5
// speedup vs baseline: 2.2065x; 1.0017x over previous
#include <cuda_runtime.h>
#include <cuda_bf16.h>
#include <math.h>
#include <stdint.h>

// Problem constants
#define Bb     2
#define Ls     4096
#define Dd     1024
#define ORD    2
#define PROJ_N (3*Dd)
#define TAPS   64
#define Mrows  (Bb*Ls)
#define KDIM   1024
#define WROWS  (PROJ_N + 3*Dd)

// ---------------- scratch (device globals) -------------------------------------
__device__ float g_proj[(size_t)Mrows*PROJ_N];
__device__ float g_h[(size_t)TAPS*Dd];
__device__ float g_v[(size_t)Mrows*Dd];
__device__ float g_u[(size_t)Mrows*Dd];
__device__ float g_xc[(size_t)Mrows*Dd];
__device__ __nv_bfloat16 g_w0[(size_t)WROWS*KDIM];
__device__ __nv_bfloat16 g_w1[(size_t)WROWS*KDIM];
__device__ __nv_bfloat16 g_a0[(size_t)Mrows*KDIM];
__device__ __nv_bfloat16 g_a1[(size_t)Mrows*KDIM];
__device__ __nv_bfloat16 g_c0[(size_t)Mrows*KDIM];
__device__ __nv_bfloat16 g_c1[(size_t)Mrows*KDIM];
__device__ __nv_bfloat16 g_v0[(size_t)Mrows*KDIM];
__device__ __nv_bfloat16 g_v1[(size_t)Mrows*KDIM];

// ---------------- helpers -------------------------------------------------------
__device__ __forceinline__ uint32_t smem_u32(const void* p) {
    uint32_t a;
    asm("{ .reg .u64 t; cvta.to.shared.u64 t, %1; cvt.u32.u64 %0, t; }" : "=r"(a) : "l"(p));
    return a;
}
__device__ __forceinline__ void ldsm4(uint32_t* r, uint32_t addr) {
    asm volatile("ldmatrix.sync.aligned.m8n8.x4.shared.b16 {%0,%1,%2,%3}, [%4];"
                 : "=r"(r[0]), "=r"(r[1]), "=r"(r[2]), "=r"(r[3]) : "r"(addr));
}
__device__ __forceinline__ void mma16816(float* c, const uint32_t* a, const uint32_t* b) {
    asm volatile(
        "mma.sync.aligned.m16n8k16.row.col.f32.bf16.bf16.f32 "
        "{%0,%1,%2,%3}, {%4,%5,%6,%7}, {%8,%9}, {%0,%1,%2,%3};"
        : "+f"(c[0]), "+f"(c[1]), "+f"(c[2]), "+f"(c[3])
        : "r"(a[0]), "r"(a[1]), "r"(a[2]), "r"(a[3]), "r"(b[0]), "r"(b[1]));
}

// ================== bf16x3 HMMA GEMM =============================================
// C[M,N] = A[M,K] @ Bt[N,K]^T (+bias).  A,B as 2 bf16 components each.
// CTA 128x128, K chunk 64, 3-stage cp.async, SW128 swizzle,
// register-level software pipeline at half-kstep granularity.
#define STAGES      3
#define CHUNK_K     64
#define STAGE_BYTES 65536
#define GEMM_SMEM   (STAGES*STAGE_BYTES)

// load A fragments (both comps, both m-tiles) for k-step kk_ into buffer buf
#define LOADA(buf, stb, kk_) do { \
    ldsm4(af[buf][0][0], (stb) + offA[0][kk_]); \
    ldsm4(af[buf][0][1], (stb) + offA[1][kk_]); \
    ldsm4(af[buf][1][0], (stb) + 16384 + offA[0][kk_]); \
    ldsm4(af[buf][1][1], (stb) + 16384 + offA[1][kk_]); \
} while (0)

// load B fragments (both comps, 4 n-tiles of half h_) for k-step kk_ into buf
#define LOADB(buf, stb, kk_, h_) do { \
    uint32_t r_[4]; \
    ldsm4(r_, (stb) + 32768 + offB[2*(h_)][kk_]); \
    bfr[buf][0][0][0]=r_[0]; bfr[buf][0][0][1]=r_[1]; \
    bfr[buf][0][1][0]=r_[2]; bfr[buf][0][1][1]=r_[3]; \
    ldsm4(r_, (stb) + 32768 + offB[2*(h_)+1][kk_]); \
    bfr[buf][0][2][0]=r_[0]; bfr[buf][0][2][1]=r_[1]; \
    bfr[buf][0][3][0]=r_[2]; bfr[buf][0][3][1]=r_[3]; \
    ldsm4(r_, (stb) + 49152 + offB[2*(h_)][kk_]); \
    bfr[buf][1][0][0]=r_[0]; bfr[buf][1][0][1]=r_[1]; \
    bfr[buf][1][1][0]=r_[2]; bfr[buf][1][1][1]=r_[3]; \
    ldsm4(r_, (stb) + 49152 + offB[2*(h_)+1][kk_]); \
    bfr[buf][1][2][0]=r_[0]; bfr[buf][1][2][1]=r_[1]; \
    bfr[buf][1][3][0]=r_[2]; bfr[buf][1][3][1]=r_[3]; \
} while (0)

__global__ void __launch_bounds__(256, 1) gemm_bf16x3_k(
    const __nv_bfloat16* __restrict__ A0, const __nv_bfloat16* __restrict__ A1,
    const __nv_bfloat16* __restrict__ B0, const __nv_bfloat16* __restrict__ B1,
    const float* __restrict__ bias, float* __restrict__ C, int ldc, int Kdim, int epi,
    const float* __restrict__ u, const float* __restrict__ xcm,
    __nv_bfloat16* __restrict__ v0, __nv_bfloat16* __restrict__ v1)
{
    extern __shared__ char smem[];
    const uint32_t stg = smem_u32(smem);
    const int tid = threadIdx.x, wid = tid >> 5, lane = tid & 31;
    const int bm = blockIdx.y * 128, bn = blockIdx.x * 128;
    const int wm = (wid & 3) * 32, wn = (wid >> 2) * 64;
    const int nchunk = Kdim / CHUNK_K;

    const __nv_bfloat16* sA0 = A0 + (size_t)bm * Kdim;
    const __nv_bfloat16* sA1 = A1 + (size_t)bm * Kdim;
    const __nv_bfloat16* sB0 = B0 + (size_t)bn * Kdim;
    const __nv_bfloat16* sB1 = B1 + (size_t)bn * Kdim;

    auto fill = [&](int chunk, int stage) {
        const uint32_t st = stg + stage * STAGE_BYTES;
        const int k0 = chunk * CHUNK_K;
        const __nv_bfloat16* gs[4] = { sA0, sA1, sB0, sB1 };
        #pragma unroll
        for (int sub = 0; sub < 4; sub++) {
            const __nv_bfloat16* g = gs[sub] + k0;
            const uint32_t db = st + sub * 16384;
            #pragma unroll
            for (int i = 0; i < 4; i++) {
                int idx = tid + i * 256;
                int row = idx >> 3, cs = idx & 7;
                const void* gp = g + (size_t)row * Kdim + cs * 8;
                uint32_t dp = db + row * 128 + ((cs ^ (row & 7)) << 4);
                asm volatile("cp.async.cg.shared.global [%0], [%1], 16;"
                             :: "r"(dp), "l"(gp) : "memory");
            }
        }
        asm volatile("cp.async.commit_group;" ::: "memory");
    };

    fill(0, 0);
    fill(1, 1);

    float acc[2][8][4];
    #pragma unroll
    for (int i = 0; i < 2; i++)
        #pragma unroll
        for (int j = 0; j < 8; j++)
            #pragma unroll
            for (int q = 0; q < 4; q++) acc[i][j][q] = 0.f;

    uint32_t offA[2][4], offB[4][4];
    #pragma unroll
    for (int mt = 0; mt < 2; mt++) {
        int row = wm + mt * 16 + (lane & 15);
        #pragma unroll
        for (int kk = 0; kk < 4; kk++) {
            int cs = kk * 2 + (lane >> 4);
            offA[mt][kk] = row * 128 + ((cs ^ (row & 7)) << 4);
        }
    }
    #pragma unroll
    for (int j = 0; j < 4; j++) {
        int n = wn + j * 16 + ((lane >> 4) << 3) + (lane & 7);
        #pragma unroll
        for (int kk = 0; kk < 4; kk++) {
            int cs = kk * 2 + ((lane >> 3) & 1);
            offB[j][kk] = n * 128 + ((cs ^ (n & 7)) << 4);
        }
    }

    for (int c = 0; c < nchunk; c++) {
        const int s = c % STAGES;
        asm volatile("cp.async.wait_group 1;" ::: "memory");
        __syncthreads();

        const int nc = c + STAGES - 1;
        if (nc < nchunk) fill(nc, nc % STAGES);

        const uint32_t st = stg + s * STAGE_BYTES;
        uint32_t af[2][2][2][4];   // [buf][comp][mt][frag]
        uint32_t bfr[2][2][4][2];  // [buf][comp][ntile][frag]

        LOADA(0, st, 0);
        LOADB(0, st, 0, 0);

        #pragma unroll
        for (int idx = 0; idx < 8; idx++) {
            const int kk = idx >> 1, h = idx & 1;
            const int ab = kk & 1, bb = idx & 1;
            if (idx < 7) {
                const int nkk = (idx + 1) >> 1, nh = (idx + 1) & 1;
                LOADB(bb ^ 1, st, nkk, nh);
                if (h == 0 && kk < 3) LOADA(ab ^ 1, st, kk + 1);
            }
            #pragma unroll
            for (int mt = 0; mt < 2; mt++)
                #pragma unroll
                for (int t = 0; t < 4; t++) {
                    const int nt = 4 * h + t;
                    mma16816(acc[mt][nt], af[ab][0][mt], bfr[bb][0][t]);  // h*h
                    mma16816(acc[mt][nt], af[ab][0][mt], bfr[bb][1][t]);  // h*l
                    mma16816(acc[mt][nt], af[ab][1][mt], bfr[bb][0][t]);  // l*h
                }
        }
    }

    // ---------------- epilogue --------------------------------------------------
    const int r0 = bm + wm + (lane >> 2);
    const int cb0 = bn + wn + (lane & 3) * 2;
    #pragma unroll
    for (int mt = 0; mt < 2; mt++) {
        #pragma unroll
        for (int nt = 0; nt < 8; nt++) {
            const int col = cb0 + nt * 8;
            const float bx = bias[col], by = bias[col + 1];
            #pragma unroll
            for (int half = 0; half < 2; half++) {
                const int row = r0 + mt * 16 + half * 8;
                float vx = acc[mt][nt][half * 2 + 0] + bx;
                float vy = acc[mt][nt][half * 2 + 1] + by;
                if (epi >= 1) {
                    const size_t idx = (size_t)row * Dd + col;
                    float2 uu = *(const float2*)(u + idx);
                    float2 xx = *(const float2*)(xcm + idx);
                    vx = uu.x * xx.x * (1.0f / (1.0f + expf(-vx)));
                    vy = uu.y * xx.y * (1.0f / (1.0f + expf(-vy)));
                    __nv_bfloat16 h0 = __float2bfloat16_rn(vx);
                    __nv_bfloat16 h1 = __float2bfloat16_rn(vy);
                    __nv_bfloat162 hh; hh.x = h0; hh.y = h1;
                    *(__nv_bfloat162*)(v0 + idx) = hh;
                    __nv_bfloat162 ll;
                    ll.x = __float2bfloat16_rn(vx - __bfloat162float(h0));
                    ll.y = __float2bfloat16_rn(vy - __bfloat162float(h1));
                    *(__nv_bfloat162*)(v1 + idx) = ll;
                }
                if (epi != 2) {
                    float2 o; o.x = vx; o.y = vy;
                    *(float2*)(C + (size_t)row * ldc + col) = o;
                }
            }
        }
    }
}

// ================== split / transpose-split ======================================
__global__ void split4_k(const float* __restrict__ s,
                         __nv_bfloat16* __restrict__ b0, __nv_bfloat16* __restrict__ b1, int n4)
{
    int i = blockIdx.x * blockDim.x + threadIdx.x;
    if (i >= n4) return;
    float4 v = ((const float4*)s)[i];
    const float* vv = (const float*)&v;
    #pragma unroll
    for (int q = 0; q < 4; q += 2) {
        __nv_bfloat16 h0 = __float2bfloat16_rn(vv[q]);
        __nv_bfloat16 h1 = __float2bfloat16_rn(vv[q + 1]);
        __nv_bfloat162 hh; hh.x = h0; hh.y = h1;
        *(__nv_bfloat162*)(b0 + (size_t)i * 4 + q) = hh;
        __nv_bfloat162 ll;
        ll.x = __float2bfloat16_rn(vv[q]     - __bfloat162float(h0));
        ll.y = __float2bfloat16_rn(vv[q + 1] - __bfloat162float(h1));
        *(__nv_bfloat162*)(b1 + (size_t)i * 4 + q) = ll;
    }
}

__global__ void tsplit_k(const float* __restrict__ W, int N, int rowoff,
                         __nv_bfloat16* __restrict__ T0, __nv_bfloat16* __restrict__ T1)
{
    __shared__ float tile[32][33];
    int n0 = blockIdx.x * 32, k0 = blockIdx.y * 32;
    int tx = threadIdx.x, ty = threadIdx.y;
    #pragma unroll
    for (int j = 0; j < 32; j += 8)
        tile[ty + j][tx] = W[(size_t)(k0 + ty + j) * N + n0 + tx];
    __syncthreads();
    #pragma unroll
    for (int j = 0; j < 32; j += 8) {
        int n = n0 + ty + j, k = k0 + tx;
        float v = tile[tx][ty + j];
        __nv_bfloat16 h = __float2bfloat16_rn(v);
        size_t o = (size_t)(rowoff + n) * KDIM + k;
        T0[o] = h;
        T1[o] = __float2bfloat16_rn(v - __bfloat162float(h));
    }
}

// ================== filter ========================================================
__device__ __forceinline__ float gelu_exact(float x) {
    return 0.5f * x * (1.0f + erff(x * 0.70710678118654752f));
}

__global__ void filter_k(const float* __restrict__ freqs,
                         const float* __restrict__ w1, const float* __restrict__ b1,
                         const float* __restrict__ w2, const float* __restrict__ b2,
                         const float* __restrict__ w3, const float* __restrict__ b3,
                         const float* __restrict__ decay, int ord,
                         float* __restrict__ h)
{
    const int n   = blockIdx.x;
    const int tid = threadIdx.x;
    const float t = (float)n / (float)(Ls - 1);
    __shared__ float h1s[64];
    __shared__ float h2s[64];
    float enc[7];
    const float* f = freqs + ord * 3;
    #pragma unroll
    for (int j = 0; j < 3; j++) {
        float ang = 6.283185307179586f * f[j] * t;
        enc[j] = sinf(ang); enc[3 + j] = cosf(ang);
    }
    enc[6] = t;
    if (tid < 64) {
        float s = b1[ord * 64 + tid];
        #pragma unroll
        for (int k = 0; k < 7; k++) s += enc[k] * w1[(ord * 7 + k) * 64 + tid];
        h1s[tid] = gelu_exact(s);
    }
    __syncthreads();
    if (tid < 64) {
        float s = b2[ord * 64 + tid];
        for (int k = 0; k < 64; k++) s += h1s[k] * w2[(ord * 64 + k) * 64 + tid];
        h2s[tid] = gelu_exact(s);
    }
    __syncthreads();
    for (int d = tid; d < Dd; d += blockDim.x) {
        float s = b3[(size_t)ord * Dd + d];
        for (int k = 0; k < 64; k++) s += h2s[k] * w3[((size_t)ord * 64 + k) * Dd + d];
        float wind = expf(-fabsf(decay[(size_t)ord * Dd + d]) * t * (float)Ls);
        h[(size_t)n * Dd + d] = s * wind;
    }
}

// ================== merged convlong + conv3 ======================================
// Per block: d-range 128 (bx), t-range CT (by), batch (bz).
//   u[b,t,d]  = sum_l hflt[l,d] * vin[b,t-l,d]      (truncated causal long conv)
//   xc[b,t,d] = depthwise3(proj ctrl slice) + bias; also bf16 split to o0/o1
#define CT 32
__global__ void __launch_bounds__(128) convs_k(
    const float* __restrict__ vin, int vstride,
    const float* __restrict__ hflt,
    float* __restrict__ u,
    const float* __restrict__ proj, int off,
    const float* __restrict__ w, const float* __restrict__ cb,
    float* __restrict__ xc,
    __nv_bfloat16* __restrict__ o0, __nv_bfloat16* __restrict__ o1)
{
    __shared__ float vs[CT + TAPS - 1][128];
    const int tx = threadIdx.x;
    const int d  = blockIdx.x * 128 + tx;
    const int t0 = blockIdx.y * CT;
    const int b  = blockIdx.z;

    #pragma unroll 5
    for (int r = 0; r < CT + TAPS - 1; r++) {
        int t = t0 - (TAPS - 1) + r;
        vs[r][tx] = (t >= 0) ? vin[((size_t)b * Ls + t) * vstride + d] : 0.f;
    }
    __syncthreads();

    float acc[CT];
    #pragma unroll
    for (int j = 0; j < CT; j++) acc[j] = 0.f;
    #pragma unroll
    for (int l0 = 0; l0 < TAPS; l0 += 16) {
        float hr[16];
        #pragma unroll
        for (int l = 0; l < 16; l++) hr[l] = hflt[(size_t)(l0 + l) * Dd + d];
        float vv[CT + 15];
        #pragma unroll
        for (int q = 0; q < CT + 15; q++) vv[q] = vs[(TAPS - 1 - 15) - l0 + q][tx];
        #pragma unroll
        for (int l = 0; l < 16; l++)
            #pragma unroll
            for (int j = 0; j < CT; j++)
                acc[j] = fmaf(vv[15 + j - l], hr[l], acc[j]);
    }
    #pragma unroll
    for (int j = 0; j < CT; j++)
        u[((size_t)b * Ls + t0 + j) * Dd + d] = acc[j];

    // conv3 on ctrl slice (independent of convlong result)
    const float wl = w[d], wc = w[Dd + d], wr = w[2 * Dd + d], cbv = cb[d];
    const float* pbase = proj + ((size_t)b * Ls + t0) * PROJ_N + off + d;
    #pragma unroll 4
    for (int j = 0; j < CT; j++) {
        int t = t0 + j;
        const float* p = pbase + (size_t)j * PROJ_N;
        float s = cbv + p[0] * wc;
        if (t > 0)      s += p[-PROJ_N] * wl;
        if (t < Ls - 1) s += p[PROJ_N]  * wr;
        size_t idx = ((size_t)b * Ls + t) * Dd + d;
        xc[idx] = s;
        __nv_bfloat16 hh = __float2bfloat16_rn(s);
        o0[idx] = hh;
        o1[idx] = __float2bfloat16_rn(s - __bfloat162float(hh));
    }
}

// =================================================================================
extern "C" void kernel_launch(void* const* d_in, const int* in_sizes, int n_in,
                              void* d_out, int out_size)
{
    const float* x    = (const float*)d_in[0];
    const float* ipw  = (const float*)d_in[1];
    const float* ipb  = (const float*)d_in[2];
    const float* opw  = (const float*)d_in[3];
    const float* opb  = (const float*)d_in[4];
    const float* fre  = (const float*)d_in[5];
    const float* w1   = (const float*)d_in[6];
    const float* b1   = (const float*)d_in[7];
    const float* w2   = (const float*)d_in[8];
    const float* b2   = (const float*)d_in[9];
    const float* w3   = (const float*)d_in[10];
    const float* b3   = (const float*)d_in[11];
    const float* dec  = (const float*)d_in[12];
    const float* cw   = (const float*)d_in[13];
    const float* cb   = (const float*)d_in[14];
    const float* gw   = (const float*)d_in[15];
    const float* gb   = (const float*)d_in[16];
    float* out = (float*)d_out;

    float *p_proj, *p_h, *p_v, *p_u, *p_xc;
    __nv_bfloat16 *p_w0, *p_w1, *p_a0, *p_a1, *p_c0, *p_c1, *p_v0, *p_v1;
    cudaGetSymbolAddress((void**)&p_proj, g_proj);
    cudaGetSymbolAddress((void**)&p_h,    g_h);
    cudaGetSymbolAddress((void**)&p_v,    g_v);
    cudaGetSymbolAddress((void**)&p_u,    g_u);
    cudaGetSymbolAddress((void**)&p_xc,   g_xc);
    cudaGetSymbolAddress((void**)&p_w0,   g_w0);
    cudaGetSymbolAddress((void**)&p_w1,   g_w1);
    cudaGetSymbolAddress((void**)&p_a0,   g_a0);
    cudaGetSymbolAddress((void**)&p_a1,   g_a1);
    cudaGetSymbolAddress((void**)&p_c0,   g_c0);
    cudaGetSymbolAddress((void**)&p_c1,   g_c1);
    cudaGetSymbolAddress((void**)&p_v0,   g_v0);
    cudaGetSymbolAddress((void**)&p_v1,   g_v1);

    cudaFuncSetAttribute(gemm_bf16x3_k, cudaFuncAttributeMaxDynamicSharedMemorySize, GEMM_SMEM);

    // split x into bf16 comps
    {
        int n4 = Mrows * KDIM / 4;
        split4_k<<<(n4 + 255) / 256, 256>>>(x, p_a0, p_a1, n4);
    }
    // transpose-split weights
    {
        dim3 b(32, 8);
        tsplit_k<<<dim3(PROJ_N / 32, KDIM / 32), b>>>(ipw, PROJ_N, 0,        p_w0, p_w1);
        tsplit_k<<<dim3(Dd / 32,     KDIM / 32), b>>>(gw,  Dd, PROJ_N,       p_w0, p_w1);
        tsplit_k<<<dim3(Dd / 32,     KDIM / 32), b>>>(gw + (size_t)Dd * Dd, Dd, PROJ_N + Dd, p_w0, p_w1);
        tsplit_k<<<dim3(Dd / 32,     KDIM / 32), b>>>(opw, Dd, PROJ_N + 2 * Dd, p_w0, p_w1);
    }

    // 1) proj = x @ in_proj_w + b
    gemm_bf16x3_k<<<dim3(PROJ_N / 128, Mrows / 128), 256, GEMM_SMEM>>>(
        p_a0, p_a1, p_w0, p_w1, ipb, p_proj, PROJ_N, KDIM, 0,
        nullptr, nullptr, nullptr, nullptr);

    for (int i = 0; i < ORD; i++) {
        filter_k<<<TAPS, 256>>>(fre, w1, b1, w2, b2, w3, b3, dec, i, p_h);

        const float* vin = (i == 0) ? p_proj : p_v;
        int vstride      = (i == 0) ? PROJ_N : Dd;
        dim3 gc(Dd / 128, Ls / CT, Bb);
        convs_k<<<gc, 128>>>(vin, vstride, p_h, p_u,
                             p_proj, (i + 1) * Dd,
                             cw + (size_t)i * 3 * Dd, cb + (size_t)i * Dd,
                             p_xc, p_c0, p_c1);

        // gate GEMM fused: v = u .* xc .* sigmoid(xc@gw + gb); epi 2 = skip fp32 v
        gemm_bf16x3_k<<<dim3(Dd / 128, Mrows / 128), 256, GEMM_SMEM>>>(
            p_c0, p_c1,
            p_w0 + (size_t)(PROJ_N + i * Dd) * KDIM,
            p_w1 + (size_t)(PROJ_N + i * Dd) * KDIM,
            gb + (size_t)i * Dd, p_v, Dd, KDIM, (i == 0) ? 1 : 2,
            p_u, p_xc, p_v0, p_v1);
    }

    // 3) out = v @ out_proj_w + b
    gemm_bf16x3_k<<<dim3(Dd / 128, Mrows / 128), 256, GEMM_SMEM>>>(
        p_v0, p_v1,
        p_w0 + (size_t)(PROJ_N + 2 * Dd) * KDIM,
        p_w1 + (size_t)(PROJ_N + 2 * Dd) * KDIM,
        opb, out, Dd, KDIM, 0,
        nullptr, nullptr, nullptr, nullptr);
}